// round 3
// baseline (speedup 1.0000x reference)
#include <cuda_runtime.h>
#include <math.h>

#define NB 512   // batch
#define NF 512   // features
#define NS 255   // splits
#define NN 511   // nodes
#define NC 21    // candidates
#define NBLK 128
#define NTHR 256

#define QSCALE 268435456.0                 // 2^28
#define QINV   3.7252902984619140625e-09f  // 2^-28

// ---------------- scratch (no allocations allowed) ----------------
__device__ unsigned long long g_qsplitI[NS * NB]; // [s][b] fixed-point accum (zeroed at end each launch)
__device__ float g_qnodeT[NN * NB];               // [n][b]
__device__ float g_ga[NN * NC];
__device__ float g_anode[NN];
__device__ unsigned g_barCnt;                     // zero-init; returns to 0 after each barrier
__device__ volatile unsigned g_barGen;            // monotonically increasing across launches (wrap-safe)

// ---------------- software grid barrier (all NBLK blocks co-resident) ----------------
__device__ __forceinline__ void gridsync()
{
    __threadfence();          // release: make this thread's writes device-visible
    __syncthreads();
    if (threadIdx.x == 0) {
        unsigned g = g_barGen;
        if (atomicAdd(&g_barCnt, 1u) == NBLK - 1u) {
            g_barCnt = 0u;
            __threadfence();
            g_barGen = g + 1u;
        } else {
            while (g_barGen == g) { }
        }
        __threadfence();      // acquire (gpu-scope fence invalidates L1D on sm_103a)
    }
    __syncthreads();
}

// ---------------- warp-collective softmin over 21 candidates ----------------
__device__ __forceinline__ void softmin_warp(int g, const float* sGa, const int* sK, float* sAgrp)
{
    int lane = threadIdx.x & 31;
    float kg = (float)sK[g];
    int c1 = 2 * g + 1, c2 = 2 * g + 2;
    float s;
    if (lane < NC) {
        float v = (1.0f - kg) * sGa[g * NC + lane];
        if (c1 < NN) v += (float)sK[c1] * sGa[c1 * NC + lane];
        if (c2 < NN) v += (float)sK[c2] * sGa[c2 * NC + lane];
        s = -100.0f * v;
    } else {
        s = -3.0e38f;
    }
    float m = s;
#pragma unroll
    for (int o = 16; o > 0; o >>= 1) m = fmaxf(m, __shfl_xor_sync(0xffffffffu, m, o));
    float e  = (lane < NC) ? __expf(s - m) : 0.0f;
    float ae = e * ((float)lane / 20.0f);
#pragma unroll
    for (int o = 16; o > 0; o >>= 1) {
        e  += __shfl_xor_sync(0xffffffffu, e, o);
        ae += __shfl_xor_sync(0xffffffffu, ae, o);
    }
    if (lane == 0) sAgrp[g] = ae / e;
}

// ==================== the fused kernel ====================
__global__ __launch_bounds__(NTHR, 1)
void fused_kernel(const float* __restrict__ x, const float* __restrict__ W,
                  const float* __restrict__ bias, float* __restrict__ out)
{
    extern __shared__ char sm[];
    int tid = threadIdx.x;
    int bid = blockIdx.x;

    // ---------------- phase 1: GEMM  qsplitT[s][b] = sum_f W[f][s]*x[b][f] ----------------
    // 128 blocks: 4 sTiles(64) x 8 bTiles(64) x ksplit 4 (K=128 each), deterministic int64 atomics.
    {
        float* As = (float*)sm;       // [64][68]
        float* Bs = As + 64 * 68;     // [64][68]
        int ks  = bid & 3;
        int pos = bid >> 2;
        int bT  = pos & 7;
        int sT  = pos >> 3;
        int sBase = sT * 64, bBase = bT * 64;
        int tr = tid >> 4, tc = tid & 15;

        float acc[4][4];
#pragma unroll
        for (int i = 0; i < 4; i++)
#pragma unroll
            for (int j = 0; j < 4; j++) acc[i][j] = 0.0f;

#pragma unroll
        for (int ch = 0; ch < 2; ch++) {
            int kc = ks * 128 + ch * 64;
            __syncthreads();
            {
                int s = tid & 63, f0 = tid >> 6;
                int gs = sBase + s;
#pragma unroll
                for (int i = 0; i < 16; i++) {
                    int f = f0 + i * 4;
                    As[f * 68 + s] = (gs < NS) ? W[(kc + f) * NS + gs] : 0.0f;
                }
                int fb = tid & 63, b0 = tid >> 6;
#pragma unroll
                for (int i = 0; i < 16; i++) {
                    int b = b0 + i * 4;
                    Bs[fb * 68 + b] = x[(bBase + b) * NF + kc + fb];
                }
            }
            __syncthreads();
#pragma unroll
            for (int f = 0; f < 64; f++) {
                float4 a4 = *(const float4*)&As[f * 68 + tr * 4];
                float4 b4 = *(const float4*)&Bs[f * 68 + tc * 4];
                float av[4] = {a4.x, a4.y, a4.z, a4.w};
                float bv[4] = {b4.x, b4.y, b4.z, b4.w};
#pragma unroll
                for (int i = 0; i < 4; i++)
#pragma unroll
                    for (int j = 0; j < 4; j++) acc[i][j] += av[i] * bv[j];
            }
        }
#pragma unroll
        for (int i = 0; i < 4; i++) {
            int s = sBase + tr * 4 + i;
            if (s < NS) {
#pragma unroll
                for (int j = 0; j < 4; j++) {
                    int b = bBase + tc * 4 + j;
                    long long q = __double2ll_rn((double)acc[i][j] * QSCALE);
                    atomicAdd(&g_qsplitI[s * NB + b], (unsigned long long)q);
                }
            }
        }
    }
    gridsync();

    // ---------------- phase 2: q_node (ancestor walk) + g_a reduction ----------------
    {
        float* sBias = (float*)sm;          // [NS]
        float* sW    = sBias + 256;         // [8][NC]
        if (tid < NS) sBias[tid] = bias[tid];
        __syncthreads();
        for (int ni = 0; ni < 4; ni++) {
            int n = bid * 4 + ni;
            if (n >= NN) break;             // uniform within block (only block 127, ni=3)
            float accs[NC];
#pragma unroll
            for (int c = 0; c < NC; c++) accs[c] = 0.0f;
#pragma unroll
            for (int rep = 0; rep < 2; rep++) {
                int b = tid + rep * 256;
                float m = 1.0f;
                int a = n;
                while (a > 0) {
                    int p = (a - 1) >> 1;
                    float q = (float)(long long)g_qsplitI[p * NB + b] * QINV + sBias[p];
                    m = fminf(m, (a == 2 * p + 1) ? -q : q);
                    a = p;
                }
                g_qnodeT[n * NB + b] = m;
                float qh = m + 0.5f;
#pragma unroll
                for (int c = 0; c < NC; c++) {
                    float d = fminf((float)c / 20.0f - qh, 0.0f);  // 0 when cand > qh
                    accs[c] = fmaf(d, d, accs[c]);
                }
            }
#pragma unroll
            for (int c = 0; c < NC; c++)
#pragma unroll
                for (int o = 16; o > 0; o >>= 1)
                    accs[c] += __shfl_down_sync(0xffffffffu, accs[c], o);
            int w = tid >> 5, l = tid & 31;
            if (l == 0) {
#pragma unroll
                for (int c = 0; c < NC; c++) sW[w * NC + c] = accs[c];
            }
            __syncthreads();
            if (tid < NC) {
                float s = 0.0f;
#pragma unroll
                for (int ww = 0; ww < 8; ww++) s += sW[ww * NC + tid];
                float ac = (float)tid / 20.0f;
                g_ga[n * NC + tid] = 0.5f * ac * ac + 0.5f * s;
            }
            __syncthreads();
        }
    }
    gridsync();

    // ---------------- phase 3: the scan (block 0; merge loop = single warp) ----------------
    if (bid == 0) {
        float* sGa   = (float*)sm;               // [NN*NC]
        float* sAgrp = sGa + NN * NC;            // [NN]
        int*   sK    = (int*)(sAgrp + NN);       // [NN]
        for (int i = tid; i < NN * NC; i += NTHR) sGa[i] = g_ga[i];
        for (int i = tid; i < NN; i += NTHR) sK[i] = 0;
        __syncthreads();
        for (int i = tid; i < NN; i += NTHR) {   // initial a_grp: k==0 -> own row softmin
            const float* r = &sGa[i * NC];
            float m = -3.0e38f;
#pragma unroll
            for (int c = 0; c < NC; c++) m = fmaxf(m, -100.0f * r[c]);
            float su = 0.0f, asu = 0.0f;
#pragma unroll
            for (int c = 0; c < NC; c++) {
                float e = __expf(-100.0f * r[c] - m);
                su += e; asu += (float)c / 20.0f * e;
            }
            sAgrp[i] = asu / su;
        }
        __syncthreads();

        if (tid < 32) {                          // warp 0 only: zero block barriers in loop
            int lane = tid;
            int applied = 0;
            for (;;) {
                float bv = -3.0e38f; int bi = NN;
#pragma unroll
                for (int i = 0; i < 16; i++) {
                    int n = lane * 16 + i;       // ascending global index -> first-argmax
                    if (n < NN) {
                        float v;
                        if (n == 0) {
                            v = sAgrp[0] - 1.0f; // k[0]==0 always; parent cap = 1
                        } else {
                            int p = (n - 1) >> 1;
                            float agp = sAgrp[p];
                            float k   = (float)sK[n];
                            float an  = (1.0f - k) * sAgrp[n] + k * agp;
                            float kp  = (float)sK[p];
                            float apar = (p > 0) ? (1.0f - kp) * agp + kp * sAgrp[(p - 1) >> 1]
                                                 : agp;
                            v = an - apar;
                        }
                        if (v > bv) { bv = v; bi = n; }
                    }
                }
#pragma unroll
                for (int o = 16; o > 0; o >>= 1) {
                    float ov = __shfl_down_sync(0xffffffffu, bv, o);
                    int   oi = __shfl_down_sync(0xffffffffu, bi, o);
                    if (ov > bv || (ov == bv && oi < bi)) { bv = ov; bi = oi; }
                }
                int t = (lane == 0) ? ((bv <= 1e-8f && bi > 0) ? bi : -1) : 0;
                t = __shfl_sync(0xffffffffu, t, 0);
                if (t < 0 || applied >= NN) break;   // fixed point / 512th body's merge discarded
                applied++;
                if (lane == 0) sK[t] += 1;
                __syncwarp();
                softmin_warp((t - 1) >> 1, sGa, sK, sAgrp);
                __syncwarp();
                softmin_warp(t, sGa, sK, sAgrp);
                __syncwarp();
            }
        }
        __syncthreads();
        for (int i = tid; i < NN; i += NTHR) {
            float an;
            if (i == 0) an = sAgrp[0];
            else {
                float k = (float)sK[i];
                an = (1.0f - k) * sAgrp[i] + k * sAgrp[(i - 1) >> 1];
            }
            g_anode[i] = an;
        }
    }
    gridsync();

    // ---------------- phase 4: transpose + clip; re-zero accumulator ----------------
    {
        float* tile = (float*)sm;   // [32][33]
        for (int it = bid; it < 256; it += NBLK) {
            int tn = it >> 4, tb = it & 15;
            int n0 = tn * 32, b0 = tb * 32;
            __syncthreads();
#pragma unroll
            for (int pass = 0; pass < 4; pass++) {
                int r = (tid >> 5) + pass * 8, c = tid & 31;
                int n = n0 + r;
                float v = 0.0f;
                if (n < NN) {
                    float q = g_qnodeT[n * NB + b0 + c];      // coalesced over b
                    v = fminf(fmaxf(q, 0.0f), g_anode[n]);
                }
                tile[r * 33 + c] = v;
            }
            __syncthreads();
#pragma unroll
            for (int pass = 0; pass < 4; pass++) {
                int r = (tid >> 5) + pass * 8, c = tid & 31;
                int n = n0 + c;
                if (n < NN) out[(b0 + r) * NN + n] = tile[c * 33 + r];  // coalesced over n
            }
        }
        // re-zero fixed-point accumulator for next launch (zero-init covers launch 1)
        ulonglong2 z; z.x = 0ULL; z.y = 0ULL;
        ulonglong2* p = (ulonglong2*)g_qsplitI;
        for (int i = bid * NTHR + tid; i < NS * NB / 2; i += NBLK * NTHR) p[i] = z;
    }
}

// ---------------- launch ----------------
extern "C" void kernel_launch(void* const* d_in, const int* in_sizes, int n_in,
                              void* d_out, int out_size)
{
    const float* x = (const float*)d_in[0];
    const float* W = (const float*)d_in[1];
    const float* b = (const float*)d_in[2];
    // d_in[3] = max_depth (fixed at 8; shapes hardcoded)

    // smem: max(gemm 34816 B, scan 47012 B, transpose 4224 B) -> 47104 B (< 48KB default cap)
    fused_kernel<<<NBLK, NTHR, 47104>>>(x, W, b, (float*)d_out);
}

// round 4
// speedup vs baseline: 1.1304x; 1.1304x over previous
#include <cuda_runtime.h>
#include <math.h>

#define NB 512   // batch
#define NF 512   // features
#define NS 255   // splits
#define NN 511   // nodes
#define NC 21    // candidates

#define QSCALE 268435456.0                 // 2^28
#define QINV   3.7252902984619140625e-09f  // 2^-28

// ---------------- scratch (no allocations allowed) ----------------
__device__ unsigned long long g_qsplitI[NS * NB]; // [s][b] fixed-point accum (zeroed at end each launch)
__device__ float g_qnodeT[NN * NB];               // [n][b]
__device__ float g_ga    [NN * NC];
__device__ float g_anode [NN];

// ================= kernel 1: split-K GEMM, transposed output =================
// qsplitT[s][b] = sum_f W[f][s] * x[b][f]   (bias added by consumers)
// grid: (ksplit=8, bTile=8, sTile=4), block 256, each block 64x64x64 panel.
// Deterministic: fixed-point int64 atomic accumulation.
__global__ __launch_bounds__(256, 2)
void gemm_kernel(const float* __restrict__ x, const float* __restrict__ W)
{
    __shared__ float As[64][68];   // [f][s]
    __shared__ float Bs[64][68];   // [f][b]

    int tid   = threadIdx.x;
    int k0    = blockIdx.x * 64;
    int bBase = blockIdx.y * 64;
    int sBase = blockIdx.z * 64;

    {
        int s = tid & 63, f0 = tid >> 6;
        int gs = sBase + s;
#pragma unroll
        for (int i = 0; i < 16; i++) {
            int f = f0 + i * 4;
            As[f][s] = (gs < NS) ? W[(k0 + f) * NS + gs] : 0.0f;
        }
        int fb = tid & 63, b0 = tid >> 6;
#pragma unroll
        for (int i = 0; i < 16; i++) {
            int b = b0 + i * 4;
            Bs[fb][b] = x[(bBase + b) * NF + k0 + fb];
        }
    }
    __syncthreads();

    int tr = tid >> 4;   // s quad
    int tc = tid & 15;   // b quad
    float acc[4][4];
#pragma unroll
    for (int i = 0; i < 4; i++)
#pragma unroll
        for (int j = 0; j < 4; j++) acc[i][j] = 0.0f;

#pragma unroll
    for (int f = 0; f < 64; f++) {
        float4 a4 = *(const float4*)&As[f][tr * 4];
        float4 b4 = *(const float4*)&Bs[f][tc * 4];
        float av[4] = {a4.x, a4.y, a4.z, a4.w};
        float bv[4] = {b4.x, b4.y, b4.z, b4.w};
#pragma unroll
        for (int i = 0; i < 4; i++)
#pragma unroll
            for (int j = 0; j < 4; j++) acc[i][j] += av[i] * bv[j];
    }

#pragma unroll
    for (int i = 0; i < 4; i++) {
        int s = sBase + tr * 4 + i;
        if (s < NS) {
#pragma unroll
            for (int j = 0; j < 4; j++) {
                int b = bBase + tc * 4 + j;
                long long q = __double2ll_rn((double)acc[i][j] * QSCALE);
                atomicAdd(&g_qsplitI[s * NB + b], (unsigned long long)q);
            }
        }
    }
}

// ================= kernel 2: q_node (ancestor walk) + g_a reduction =================
__global__ __launch_bounds__(256)
void ga_kernel(const float* __restrict__ bias)
{
    int n   = blockIdx.x;
    int tid = threadIdx.x;

    float accs[NC];
#pragma unroll
    for (int c = 0; c < NC; c++) accs[c] = 0.0f;

#pragma unroll
    for (int rep = 0; rep < 2; rep++) {
        int b = tid + rep * 256;
        float m = 1.0f;
        int a = n;
        while (a > 0) {
            int p = (a - 1) >> 1;
            float q = (float)(long long)g_qsplitI[p * NB + b] * QINV + bias[p];
            m = fminf(m, (a == 2 * p + 1) ? -q : q);
            a = p;
        }
        g_qnodeT[n * NB + b] = m;
        float qh = m + 0.5f;
#pragma unroll
        for (int c = 0; c < NC; c++) {
            float d = fminf((float)c * (1.0f / 20.0f) - qh, 0.0f);
            accs[c] = fmaf(d, d, accs[c]);
        }
    }

#pragma unroll
    for (int c = 0; c < NC; c++)
#pragma unroll
        for (int o = 16; o > 0; o >>= 1)
            accs[c] += __shfl_down_sync(0xffffffffu, accs[c], o);

    __shared__ float sW[8][NC];
    int w = tid >> 5, l = tid & 31;
    if (l == 0) {
#pragma unroll
        for (int c = 0; c < NC; c++) sW[w][c] = accs[c];
    }
    __syncthreads();
    if (tid < NC) {
        float s = 0.0f;
#pragma unroll
        for (int ww = 0; ww < 8; ww++) s += sW[ww][tid];
        float ac = (float)tid * (1.0f / 20.0f);
        g_ga[n * NC + tid] = 0.5f * ac * ac + 0.5f * s;
    }
}

// ================= kernel 3: the scan (warp-serial merge loop) =================
__device__ __forceinline__ void softmin_warp(int g, const float* sGa, const int* sK, float* sAgrp)
{
    int lane = threadIdx.x & 31;
    float kg = (float)sK[g];
    int c1 = 2 * g + 1, c2 = 2 * g + 2;
    float s;
    if (lane < NC) {
        float v = (1.0f - kg) * sGa[g * NC + lane];
        if (c1 < NN) v += (float)sK[c1] * sGa[c1 * NC + lane];
        if (c2 < NN) v += (float)sK[c2] * sGa[c2 * NC + lane];
        s = -100.0f * v;
    } else {
        s = -3.0e38f;
    }
    float m = s;
#pragma unroll
    for (int o = 16; o > 0; o >>= 1) m = fmaxf(m, __shfl_xor_sync(0xffffffffu, m, o));
    float e  = (lane < NC) ? __expf(s - m) : 0.0f;
    float ae = e * ((float)lane * (1.0f / 20.0f));
#pragma unroll
    for (int o = 16; o > 0; o >>= 1) {
        e  += __shfl_xor_sync(0xffffffffu, e, o);
        ae += __shfl_xor_sync(0xffffffffu, ae, o);
    }
    if (lane == 0) sAgrp[g] = ae / e;
}

__global__ __launch_bounds__(256)
void scan_kernel()
{
    __shared__ float sGa[NN * NC];   // 42924 B
    __shared__ float sAgrp[NN];
    __shared__ int   sK[NN];

    int tid = threadIdx.x;

    for (int i = tid; i < NN * NC; i += 256) sGa[i] = g_ga[i];
    for (int i = tid; i < NN; i += 256) sK[i] = 0;
    __syncthreads();

    // initial a_grp: k==0 everywhere -> softmin of own row
    for (int i = tid; i < NN; i += 256) {
        const float* r = &sGa[i * NC];
        float m = -3.0e38f;
#pragma unroll
        for (int c = 0; c < NC; c++) m = fmaxf(m, -100.0f * r[c]);
        float su = 0.0f, asu = 0.0f;
#pragma unroll
        for (int c = 0; c < NC; c++) {
            float e = __expf(-100.0f * r[c] - m);
            su += e; asu += (float)c * (1.0f / 20.0f) * e;
        }
        sAgrp[i] = asu / su;
    }
    __syncthreads();

    if (tid < 32) {      // single warp runs the whole merge loop; no block barriers
        int lane = tid;
        int applied = 0;
        for (;;) {
            float bv = -3.0e38f; int bi = NN;
#pragma unroll
            for (int i = 0; i < 16; i++) {
                int n = lane * 16 + i;     // ascending index -> first-argmax semantics
                if (n < NN) {
                    float v;
                    if (n == 0) {
                        v = sAgrp[0] - 1.0f;     // k[0]==0 always; root cap = 1
                    } else {
                        int p = (n - 1) >> 1;
                        float agp = sAgrp[p];
                        float k   = (float)sK[n];
                        float an  = (1.0f - k) * sAgrp[n] + k * agp;
                        float kp  = (float)sK[p];
                        float apar = (p > 0) ? (1.0f - kp) * agp + kp * sAgrp[(p - 1) >> 1]
                                             : agp;
                        v = an - apar;
                    }
                    if (v > bv) { bv = v; bi = n; }
                }
            }
#pragma unroll
            for (int o = 16; o > 0; o >>= 1) {
                float ov = __shfl_down_sync(0xffffffffu, bv, o);
                int   oi = __shfl_down_sync(0xffffffffu, bi, o);
                if (ov > bv || (ov == bv && oi < bi)) { bv = ov; bi = oi; }
            }
            int t = (lane == 0) ? ((bv <= 1e-8f && bi > 0) ? bi : -1) : 0;
            t = __shfl_sync(0xffffffffu, t, 0);
            if (t < 0 || applied >= NN) break;   // fixed point / 512th body's merge discarded
            applied++;
            if (lane == 0) sK[t] += 1;
            __syncwarp();
            softmin_warp((t - 1) >> 1, sGa, sK, sAgrp);
            __syncwarp();
            softmin_warp(t, sGa, sK, sAgrp);
            __syncwarp();
        }
    }
    __syncthreads();

    for (int i = tid; i < NN; i += 256) {
        float an;
        if (i == 0) an = sAgrp[0];
        else {
            float k = (float)sK[i];
            an = (1.0f - k) * sAgrp[i] + k * sAgrp[(i - 1) >> 1];
        }
        g_anode[i] = an;
    }
}

// ================= kernel 4: transposed trajectory + accumulator re-zero =================
// 256 blocks, one 32x32 tile each (16 n-tiles x 16 b-tiles); coalesced load AND store.
__global__ __launch_bounds__(256)
void traj_kernel(float* __restrict__ out)
{
    __shared__ float tile[32][33];
    int tid = threadIdx.x;
    int tn = blockIdx.x >> 4, tb = blockIdx.x & 15;
    int n0 = tn * 32, b0 = tb * 32;

#pragma unroll
    for (int pass = 0; pass < 4; pass++) {
        int r = (tid >> 5) + pass * 8, c = tid & 31;
        int n = n0 + r;
        float v = 0.0f;
        if (n < NN) {
            float q = g_qnodeT[n * NB + b0 + c];          // coalesced over b
            v = fminf(fmaxf(q, 0.0f), g_anode[n]);
        }
        tile[r][c] = v;
    }
    __syncthreads();
#pragma unroll
    for (int pass = 0; pass < 4; pass++) {
        int r = (tid >> 5) + pass * 8, c = tid & 31;
        int n = n0 + c;
        if (n < NN) out[(b0 + r) * NN + n] = tile[c][r];  // coalesced over n
    }

    // re-zero fixed-point accumulator for next launch (zero-init covers launch 1)
    ulonglong2 z; z.x = 0ULL; z.y = 0ULL;
    ulonglong2* p = (ulonglong2*)g_qsplitI;
    for (int i = blockIdx.x * 256 + tid; i < NS * NB / 2; i += 256 * 256) p[i] = z;
}

// ---------------- launch ----------------
extern "C" void kernel_launch(void* const* d_in, const int* in_sizes, int n_in,
                              void* d_out, int out_size)
{
    const float* x = (const float*)d_in[0];
    const float* W = (const float*)d_in[1];
    const float* b = (const float*)d_in[2];
    // d_in[3] = max_depth (fixed at 8; shapes hardcoded)

    gemm_kernel<<<dim3(8, 8, 4), 256>>>(x, W);
    ga_kernel  <<<NN, 256>>>(b);
    scan_kernel<<<1, 256>>>();
    traj_kernel<<<256, 256>>>((float*)d_out);
}